// round 5
// baseline (speedup 1.0000x reference)
#include <cuda_runtime.h>

// Net_24395414241687 — GNN ending in log_softmax over a length-1 axis
// => output is identically zeros([1024, 1]). Entire network is dead code;
// only mandatory work is un-poisoning d_out (0xAA-filled by harness).
//
// Measured ladder:
//   R1 grid=4 kernel node:   4.86us e2e
//   R2 cudaMemsetAsync node: 3.94us e2e  <- best
//   R3 1-CTA kernel node:    4.61us e2e  (kernel-node front-end ~3.3us, grid-invariant)
//   R4 memset re-bench:      4.00us e2e  (floor confirmed, rel_err=0 exact)
// R5: last untested node type — D2D memcpy from a zero-initialized
// __device__ global (module-load zero-init guaranteed; no allocation).
// Prediction: neutral-to-worse vs memset; if >=4.0us, memset is final.

__device__ float g_zeros[1024];  // zero-initialized at module load, never written

extern "C" void kernel_launch(void* const* d_in, const int* in_sizes, int n_in,
                              void* d_out, int out_size) {
    (void)d_in; (void)in_sizes; (void)n_in;
    size_t bytes = (size_t)out_size * sizeof(float);
    void* src = nullptr;
    if (bytes <= sizeof(g_zeros) &&
        cudaGetSymbolAddress(&src, g_zeros) == cudaSuccess) {
        cudaMemcpyAsync(d_out, src, bytes, cudaMemcpyDeviceToDevice, 0);
    } else {
        cudaMemsetAsync(d_out, 0, bytes, 0);
    }
}

// round 6
// speedup vs baseline: 1.3458x; 1.3458x over previous
#include <cuda_runtime.h>

// Net_24395414241687 — two-layer NNConv GNN + readout ending in
// log_softmax over axis=1 of a [G, 1] = [1024, 1] tensor.
//
// log_softmax over a length-1 axis is identically zero:
//   log_softmax(x) = x - logsumexp(x) = x - x = 0  (bit-exact in JAX's
//   max-subtracted formulation; all upstream values are finite).
// The reference output is therefore exactly zeros([1024, 1]) for every
// input — the entire GNN pipeline is dead code. The only mandatory work
// is un-poisoning d_out (harness fills it with 0xAA before timing).
//
// Node-type search (all graph-capturable write mechanisms measured):
//   R1 grid=4 kernel node:   4.86us e2e
//   R3 1-CTA kernel node:    4.61us e2e  (kernel-node front-end ~3.3us, grid-invariant)
//   R5 D2D memcpy node:      4.61us e2e
//   R2/R4 memset node:       3.94 / 4.00us e2e  <- floor, rel_err=0 exact
// Remaining e2e is the harness's single-node graph-replay dispatch.
// FINAL: cudaMemsetAsync node.

extern "C" void kernel_launch(void* const* d_in, const int* in_sizes, int n_in,
                              void* d_out, int out_size) {
    (void)d_in; (void)in_sizes; (void)n_in;
    cudaMemsetAsync(d_out, 0, (size_t)out_size * sizeof(float), 0);
}